// round 16
// baseline (speedup 1.0000x reference)
#include <cuda_runtime.h>
#include <cuda_fp16.h>

#define BB 2
#define SS 2048
#define DD 256
#define HH 8
#define DHD 32

// Scratch (allocation-free: device globals)
__device__ __half g_q[BB*HH*SS*DHD];
__device__ __half g_k[BB*HH*SS*DHD];
__device__ __half g_v[BB*HH*SS*DHD];
__device__ __half g_ctx[BB*SS*DD];
__device__ __half g_xh[BB*SS*DD];        // x converted to fp16
__device__ __half g_wh[3*DD*DD];         // wq|wk|wv fp16
__device__ __half g_wch[DD*DD];          // wc fp16

// ---------------------------------------------------------------------------
// helpers
// ---------------------------------------------------------------------------
__device__ __forceinline__ void mma_f16(float c[4], const unsigned a[4],
                                        unsigned b0, unsigned b1) {
    asm volatile(
        "mma.sync.aligned.m16n8k16.row.col.f32.f16.f16.f32 "
        "{%0,%1,%2,%3},{%4,%5,%6,%7},{%8,%9},{%0,%1,%2,%3};"
        : "+f"(c[0]), "+f"(c[1]), "+f"(c[2]), "+f"(c[3])
        : "r"(a[0]), "r"(a[1]), "r"(a[2]), "r"(a[3]), "r"(b0), "r"(b1));
}

__device__ __forceinline__ void ldsm_x2_t(unsigned& r0, unsigned& r1, const void* p) {
    unsigned addr = (unsigned)__cvta_generic_to_shared(p);
    asm volatile("ldmatrix.sync.aligned.m8n8.x2.trans.shared.b16 {%0,%1}, [%2];"
                 : "=r"(r0), "=r"(r1) : "r"(addr));
}

__device__ __forceinline__ float2 h2f(unsigned u) {
    return __half22float2(*(__half2*)&u);
}

__device__ __forceinline__ void cp16(void* dst, const void* src) {
    unsigned d = (unsigned)__cvta_generic_to_shared(dst);
    asm volatile("cp.async.cg.shared.global [%0], [%1], 16;" :: "r"(d), "l"(src));
}
#define CP_COMMIT() asm volatile("cp.async.commit_group;")
#define CP_WAIT1()  asm volatile("cp.async.wait_group 1;")
#define CP_WAIT0()  asm volatile("cp.async.wait_group 0;")

// ---------------------------------------------------------------------------
// fp32 -> fp16 conversion prologue (x, wq, wk, wv, wc)
// ---------------------------------------------------------------------------
__global__ __launch_bounds__(256) void convert_kernel(
    const float* __restrict__ x,
    const float* __restrict__ wq, const float* __restrict__ wk,
    const float* __restrict__ wv, const float* __restrict__ wc)
{
    int t = blockIdx.x * 256 + threadIdx.x;
    int e = t * 4;
    const float* src;
    __half* dst;
    if (e < BB*SS*DD) {
        src = x + e; dst = g_xh + e;
    } else {
        int r = e - BB*SS*DD;
        int wsel = r >> 16;
        int off = r & 65535;
        src = (wsel == 0 ? wq : wsel == 1 ? wk : wsel == 2 ? wv : wc) + off;
        dst = (wsel == 3 ? g_wch : g_wh + wsel * 65536) + off;
    }
    float4 v = *(const float4*)src;
    __half2* d2 = (__half2*)dst;
    d2[0] = __floats2half2_rn(v.x, v.y);
    d2[1] = __floats2half2_rn(v.z, v.w);
}

// ---------------------------------------------------------------------------
// fp16 GEMM staging for the projections: CTA tile M=64, N=128, k-chunk 32.
// ---------------------------------------------------------------------------
__device__ __forceinline__ void stage_gemm(const __half* A, const __half* B,
                                           __half* As, __half* Bs,
                                           int mt0, int nbase, int c, int tid)
{
    {   int row = tid >> 2, seg = tid & 3;
        cp16(As + row * 40 + seg * 8, A + (size_t)(mt0 + row) * 256 + c * 32 + seg * 8); }
    #pragma unroll
    for (int i = 0; i < 2; i++) {
        int id = i * 256 + tid;
        int row = id >> 2, seg = id & 3;
        cp16(Bs + row * 40 + seg * 8, B + (size_t)(nbase + row) * 256 + c * 32 + seg * 8);
    }
    CP_COMMIT();
}

// ---------------------------------------------------------------------------
// QKV projection via fp16 mma
// ---------------------------------------------------------------------------
__global__ __launch_bounds__(256, 2) void qkv_mma_kernel(
    const float* __restrict__ bq, const float* __restrict__ bk,
    const float* __restrict__ bv)
{
    __shared__ __half As[2][64*40];
    __shared__ __half Bs[2][128*40];
    const int tid = threadIdx.x, w = tid >> 5, lane = tid & 31;
    const int g = lane >> 2, tg = lane & 3;
    const int warpM = w >> 2, warpN = w & 3;
    const int mt0 = blockIdx.x * 64;
    const int y = blockIdx.y;
    const int wsel = y >> 1;
    const int nbase = (y & 1) * 128;
    const __half* Bw = g_wh + wsel * DD * DD;
    const float* bias = wsel == 0 ? bq : (wsel == 1 ? bk : bv);
    __half* dst = wsel == 0 ? g_q : (wsel == 1 ? g_k : g_v);

    float acc[2][4][4] = {};

    stage_gemm(g_xh, Bw, As[0], Bs[0], mt0, nbase, 0, tid);
    stage_gemm(g_xh, Bw, As[1], Bs[1], mt0, nbase, 1, tid);
    for (int c = 0; c < 8; c++) {
        if (c < 7) CP_WAIT1(); else CP_WAIT0();
        __syncthreads();
        const __half* Ab = As[c & 1];
        const __half* Bb = Bs[c & 1];
        #pragma unroll
        for (int ks = 0; ks < 2; ks++) {
            unsigned a[2][4], bf[4][2];
            #pragma unroll
            for (int mt = 0; mt < 2; mt++) {
                const __half* ar  = Ab + (warpM*32 + mt*16 + g) * 40 + ks*16 + 2*tg;
                const __half* ar8 = ar + 8 * 40;
                a[mt][0] = *(const unsigned*)ar;       a[mt][1] = *(const unsigned*)ar8;
                a[mt][2] = *(const unsigned*)(ar + 8); a[mt][3] = *(const unsigned*)(ar8 + 8);
            }
            #pragma unroll
            for (int nt = 0; nt < 4; nt++) {
                const __half* br = Bb + (warpN*32 + nt*8 + g) * 40 + ks*16 + 2*tg;
                bf[nt][0] = *(const unsigned*)br;
                bf[nt][1] = *(const unsigned*)(br + 8);
            }
            #pragma unroll
            for (int mt = 0; mt < 2; mt++)
                #pragma unroll
                for (int nt = 0; nt < 4; nt++)
                    mma_f16(acc[mt][nt], a[mt], bf[nt][0], bf[nt][1]);
        }
        __syncthreads();
        if (c + 2 < 8) stage_gemm(g_xh, Bw, As[c & 1], Bs[c & 1], mt0, nbase, c + 2, tid);
    }

    #pragma unroll
    for (int mt = 0; mt < 2; mt++)
        #pragma unroll
        for (int hf = 0; hf < 2; hf++) {
            int m = mt0 + warpM*32 + mt*16 + g + hf*8;
            int bidx = m >> 11, s = m & 2047;
            #pragma unroll
            for (int nt = 0; nt < 4; nt++) {
                int n = nbase + warpN*32 + nt*8 + 2*tg;
                float c0 = acc[mt][nt][hf*2+0] + bias[n];
                float c1 = acc[mt][nt][hf*2+1] + bias[n+1];
                int h = n >> 5, dh = n & 31;
                *(__half2*)&dst[(((size_t)(bidx*HH + h) * SS + s) * DHD) + dh] =
                    __floats2half2_rn(c0, c1);
            }
        }
}

// ---------------------------------------------------------------------------
// Output projection via fp16 mma
// ---------------------------------------------------------------------------
__global__ __launch_bounds__(256, 2) void proj_mma_kernel(
    const float* __restrict__ bc, float* __restrict__ out)
{
    __shared__ __half As[2][64*40];
    __shared__ __half Bs[2][128*40];
    const int tid = threadIdx.x, w = tid >> 5, lane = tid & 31;
    const int g = lane >> 2, tg = lane & 3;
    const int warpM = w >> 2, warpN = w & 3;
    const int mt0 = blockIdx.x * 64;
    const int nbase = blockIdx.y * 128;

    float acc[2][4][4] = {};

    stage_gemm(g_ctx, g_wch, As[0], Bs[0], mt0, nbase, 0, tid);
    stage_gemm(g_ctx, g_wch, As[1], Bs[1], mt0, nbase, 1, tid);
    for (int c = 0; c < 8; c++) {
        if (c < 7) CP_WAIT1(); else CP_WAIT0();
        __syncthreads();
        const __half* Ab = As[c & 1];
        const __half* Bb = Bs[c & 1];
        #pragma unroll
        for (int ks = 0; ks < 2; ks++) {
            unsigned a[2][4], bf[4][2];
            #pragma unroll
            for (int mt = 0; mt < 2; mt++) {
                const __half* ar  = Ab + (warpM*32 + mt*16 + g) * 40 + ks*16 + 2*tg;
                const __half* ar8 = ar + 8 * 40;
                a[mt][0] = *(const unsigned*)ar;       a[mt][1] = *(const unsigned*)ar8;
                a[mt][2] = *(const unsigned*)(ar + 8); a[mt][3] = *(const unsigned*)(ar8 + 8);
            }
            #pragma unroll
            for (int nt = 0; nt < 4; nt++) {
                const __half* br = Bb + (warpN*32 + nt*8 + g) * 40 + ks*16 + 2*tg;
                bf[nt][0] = *(const unsigned*)br;
                bf[nt][1] = *(const unsigned*)(br + 8);
            }
            #pragma unroll
            for (int mt = 0; mt < 2; mt++)
                #pragma unroll
                for (int nt = 0; nt < 4; nt++)
                    mma_f16(acc[mt][nt], a[mt], bf[nt][0], bf[nt][1]);
        }
        __syncthreads();
        if (c + 2 < 8) stage_gemm(g_ctx, g_wch, As[c & 1], Bs[c & 1], mt0, nbase, c + 2, tid);
    }

    #pragma unroll
    for (int mt = 0; mt < 2; mt++)
        #pragma unroll
        for (int hf = 0; hf < 2; hf++) {
            int m = mt0 + warpM*32 + mt*16 + g + hf*8;
            #pragma unroll
            for (int nt = 0; nt < 4; nt++) {
                int n = nbase + warpN*32 + nt*8 + 2*tg;
                float c0 = acc[mt][nt][hf*2+0] + bc[n];
                float c1 = acc[mt][nt][hf*2+1] + bc[n+1];
                *(float2*)&out[(size_t)m * 256 + n] = make_float2(c0, c1);
            }
        }
}

// ---------------------------------------------------------------------------
// Attention v7: 32-row q tiles, log2-domain scores, half2 softmax (h2exp2),
// head-mean RMW fused into the PV phases (overlaps L2 with tensor work).
// smem:
//   sS   [32][2056] fp16 = 131584  (scores/probs; aliased as sRd after PV)
//   buf0/buf1: 256 rows x 40 halfs = 20480B each
//   sQ   [32][40] fp16 = 2560        total 175104
// ---------------------------------------------------------------------------
#define SSH 2056
#define SMEM_BYTES (32*SSH*2 + 2*20480 + 32*40*2)

__device__ __forceinline__ void stage_kv(const __half* src, __half* dst, int tid) {
    #pragma unroll
    for (int i = 0; i < 2; i++) {
        int id = i * 512 + tid;
        int row = id >> 2, seg = id & 3;
        cp16(dst + row * 40 + seg * 8, src + row * 32 + seg * 8);
    }
    CP_COMMIT();
}

__global__ __launch_bounds__(512, 1) void attn_kernel(float* __restrict__ attn_out)
{
    extern __shared__ char sm[];
    __half* sS = (__half*)sm;                         // 32 x 2056
    float*  sRd = (float*)sm;                         // aliases sS (dead at reduction)
    __half* buf0 = (__half*)(sm + 32 * SSH * 2);      // 256 x 40
    __half* buf1 = buf0 + 10240;
    __half* sQ   = buf1 + 10240;                      // 32 x 40
    __shared__ float s_invl[32];

    const int tid  = threadIdx.x;
    const int w    = tid >> 5;       // warp 0..15
    const int lane = tid & 31;
    const int g    = lane >> 2;
    const int tg   = lane & 3;
    const int b  = blockIdx.x >> 6;
    const int q0 = (blockIdx.x & 63) << 5;

    float* ap = attn_out + (size_t)(b * SS + q0) * SS;

    // prefetch K tiles 0,1 of head 0
    {
        const __half* kb0 = g_k + (size_t)(b * HH) * SS * DHD;
        stage_kv(kb0, buf0, tid);
        stage_kv(kb0 + 8192, buf1, tid);
    }

    for (int h = 0; h < HH; h++) {
        const __half* qb = g_q + ((size_t)(b * HH + h) * SS + q0) * DHD;
        const __half* kb = g_k + (size_t)(b * HH + h) * SS * DHD;
        const __half* vb = g_v + (size_t)(b * HH + h) * SS * DHD;
        const __half* kbn = g_k + (size_t)(b * HH + ((h + 1) & 7)) * SS * DHD;

        // --- Q tile (32x32), scale by log2(e)/sqrt(32): scores in log2 domain ---
        const float scale = 0.17677669529663687f * 1.4426950408889634f;
        {
            int r = tid >> 4, c2 = (tid & 15) * 2;
            float2 f = __half22float2(*(const __half2*)(qb + r * 32 + c2));
            *(__half2*)(sQ + r * 40 + c2) = __floats2half2_rn(f.x * scale, f.y * scale);
        }

        // --- scores: 8 tiles of 256 keys; warp owns 16-key n-slice per tile ---
        unsigned qa[2][2][4];     // [mtile][kc][frag]
        for (int kt = 0; kt < 8; kt++) {
            CP_WAIT1();
            __syncthreads();
            const __half* sK = (kt & 1) ? buf1 : buf0;
            if (kt == 0) {
                #pragma unroll
                for (int mt = 0; mt < 2; mt++)
                    #pragma unroll
                    for (int kc = 0; kc < 2; kc++) {
                        const __half* qr  = sQ + (mt*16 + g) * 40 + kc * 16 + 2 * tg;
                        const __half* qr8 = qr + 8 * 40;
                        qa[mt][kc][0] = *(const unsigned*)qr;
                        qa[mt][kc][1] = *(const unsigned*)qr8;
                        qa[mt][kc][2] = *(const unsigned*)(qr + 8);
                        qa[mt][kc][3] = *(const unsigned*)(qr8 + 8);
                    }
            }
            #pragma unroll
            for (int nt = 0; nt < 2; nt++) {
                const int n0 = w * 16 + nt * 8;
                const __half* krow = sK + (n0 + g) * 40;
                unsigned b0[2], b1[2];
                #pragma unroll
                for (int kc = 0; kc < 2; kc++) {
                    b0[kc] = *(const unsigned*)(krow + kc * 16 + 2 * tg);
                    b1[kc] = *(const unsigned*)(krow + kc * 16 + 2 * tg + 8);
                }
                #pragma unroll
                for (int mt = 0; mt < 2; mt++) {
                    float c[4] = {0.f, 0.f, 0.f, 0.f};
                    #pragma unroll
                    for (int kc = 0; kc < 2; kc++)
                        mma_f16(c, qa[mt][kc], b0[kc], b1[kc]);
                    const int col = kt * 256 + n0 + tg * 2;
                    *(__half2*)(sS + (mt*16 + g) * SSH + col)     = __floats2half2_rn(c[0], c[1]);
                    *(__half2*)(sS + (mt*16 + g + 8) * SSH + col) = __floats2half2_rn(c[2], c[3]);
                }
            }
            __syncthreads();
            if (kt < 6)       stage_kv(kb + (size_t)(kt + 2) * 8192, (kt & 1) ? buf1 : buf0, tid);
            else if (kt == 6) stage_kv(vb, buf0, tid);
            else              stage_kv(vb + 8192, buf1, tid);
        }
        __syncthreads();

        // --- softmax in half2 domain: p = 2^(s - mx); fp32 row sums ---
        {
            const int row = tid >> 4, j = tid & 15;   // 32 rows x 16 threads
            uint4* r4 = (uint4*)(sS + (size_t)row * SSH);
            __half2 mx2 = __float2half2_rn(-10000.f);
            for (int k = j; k < 256; k += 16) {
                uint4 u = r4[k];
                __half2 a = *(__half2*)&u.x, bb = *(__half2*)&u.y;
                __half2 c = *(__half2*)&u.z, d = *(__half2*)&u.w;
                mx2 = __hmax2(mx2, __hmax2(__hmax2(a, bb), __hmax2(c, d)));
            }
            #pragma unroll
            for (int o = 8; o; o >>= 1) {
                unsigned v = __shfl_xor_sync(0xffffffffu, *(unsigned*)&mx2, o);
                mx2 = __hmax2(mx2, *(__half2*)&v);
            }
            __half mx = __hmax(__low2half(mx2), __high2half(mx2));
            mx2 = __half2half2(mx);
            float sum = 0.f;
            for (int k = j; k < 256; k += 16) {
                uint4 u = r4[k];
                __half2 e0 = h2exp2(__hsub2(*(__half2*)&u.x, mx2));
                __half2 e1 = h2exp2(__hsub2(*(__half2*)&u.y, mx2));
                __half2 e2 = h2exp2(__hsub2(*(__half2*)&u.z, mx2));
                __half2 e3 = h2exp2(__hsub2(*(__half2*)&u.w, mx2));
                float2 f0 = __half22float2(e0), f1 = __half22float2(e1);
                float2 f2 = __half22float2(e2), f3 = __half22float2(e3);
                sum += (f0.x + f0.y) + (f1.x + f1.y) + (f2.x + f2.y) + (f3.x + f3.y);
                u.x = *(unsigned*)&e0; u.y = *(unsigned*)&e1;
                u.z = *(unsigned*)&e2; u.w = *(unsigned*)&e3;
                r4[k] = u;
            }
            #pragma unroll
            for (int o = 8; o; o >>= 1) sum += __shfl_xor_sync(0xffffffffu, sum, o);
            if (j == 0) s_invl[row] = 1.0f / sum;
        }
        __syncthreads();

        // --- PV (8 phases of 256 k) with fused head-mean RMW per phase ---
        float oc[2][4][4] = {};
        for (int p = 0; p < 8; p++) {
            CP_WAIT1();
            __syncthreads();
            const __half* sVh = (p & 1) ? buf1 : buf0;
            const int kr  = w * 16;
            const int ksg = p * 256 + kr;
            unsigned pa[2][4];
            #pragma unroll
            for (int mt = 0; mt < 2; mt++) {
                pa[mt][0] = *(const unsigned*)(sS + (mt*16 + g) * SSH + ksg + 2 * tg);
                pa[mt][1] = *(const unsigned*)(sS + (mt*16 + g + 8) * SSH + ksg + 2 * tg);
                pa[mt][2] = *(const unsigned*)(sS + (mt*16 + g) * SSH + ksg + 2 * tg + 8);
                pa[mt][3] = *(const unsigned*)(sS + (mt*16 + g + 8) * SSH + ksg + 2 * tg + 8);
            }
            const __half* vrow = sVh + (kr + (lane & 15)) * 40;
            #pragma unroll
            for (int nt = 0; nt < 4; nt++) {
                unsigned b0, b1;
                ldsm_x2_t(b0, b1, vrow + nt * 8);
                #pragma unroll
                for (int mt = 0; mt < 2; mt++)
                    mma_f16(oc[mt][nt], pa[mt], b0, b1);
            }
            // fused mean RMW for this phase's 64 float4 columns per row
            {
                float4* a4 = (float4*)ap;
                #pragma unroll
                for (int it = 0; it < 4; it++) {
                    int t = it * 512 + tid;
                    int r = t >> 6, c = t & 63;
                    int col4 = p * 64 + c;
                    uint2 u = *(const uint2*)(sS + (size_t)r * SSH + col4 * 4);
                    float2 p0 = h2f(u.x), p1 = h2f(u.y);
                    float f = s_invl[r] * 0.125f;
                    float4 v = make_float4(p0.x * f, p0.y * f, p1.x * f, p1.y * f);
                    if (h == 0) {
                        a4[r * 512 + col4] = v;
                    } else {
                        float4 o = a4[r * 512 + col4];
                        o.x += v.x; o.y += v.y; o.z += v.z; o.w += v.w;
                        a4[r * 512 + col4] = o;
                    }
                }
            }
            __syncthreads();
            if (p < 6)       stage_kv(vb + (size_t)(p + 2) * 8192, (p & 1) ? buf1 : buf0, tid);
            else if (p == 6) stage_kv(kbn, buf0, tid);
            else             stage_kv(kbn + 8192, buf1, tid);
        }
        __syncthreads();   // PV consumers of sS done -> sRd may alias it

        // --- cross-warp reduction of the 16 k-partials (sRd aliases sS) ---
        #pragma unroll
        for (int mt = 0; mt < 2; mt++)
            #pragma unroll
            for (int nt = 0; nt < 4; nt++) {
                const int col = nt * 8 + tg * 2;
                sRd[w * 1024 + (mt*16 + g) * 32 + col]           = oc[mt][nt][0];
                sRd[w * 1024 + (mt*16 + g) * 32 + col + 1]       = oc[mt][nt][1];
                sRd[w * 1024 + (mt*16 + g + 8) * 32 + col]       = oc[mt][nt][2];
                sRd[w * 1024 + (mt*16 + g + 8) * 32 + col + 1]   = oc[mt][nt][3];
            }
        __syncthreads();
        for (int o = tid; o < 1024; o += 512) {
            int r = o >> 5, d = o & 31;
            float s = 0.f;
            #pragma unroll
            for (int e = 0; e < 16; e++) s += sRd[e * 1024 + o];
            g_ctx[(size_t)(b * SS + q0 + r) * DD + h * DHD + d] = __float2half(s * s_invl[r]);
        }
        __syncthreads();   // protect sRd/sQ/sS before next head
    }
    CP_WAIT0();   // drain trailing (dummy) prefetch before exit
}

// ---------------------------------------------------------------------------
extern "C" void kernel_launch(void* const* d_in, const int* in_sizes, int n_in,
                              void* d_out, int out_size)
{
    const float* x  = (const float*)d_in[0];
    const float* wq = (const float*)d_in[1];
    const float* bq = (const float*)d_in[2];
    const float* wk = (const float*)d_in[3];
    const float* bk = (const float*)d_in[4];
    const float* wv = (const float*)d_in[5];
    const float* bv = (const float*)d_in[6];
    const float* wc = (const float*)d_in[7];
    const float* bc = (const float*)d_in[8];

    float* out  = (float*)d_out;
    float* attn = out + (size_t)BB * SS * DD;

    convert_kernel<<<1280, 256>>>(x, wq, wk, wv, wc);
    qkv_mma_kernel<<<dim3(64, 6), 256>>>(bq, bk, bv);

    cudaFuncSetAttribute(attn_kernel,
                         cudaFuncAttributeMaxDynamicSharedMemorySize,
                         SMEM_BYTES);
    attn_kernel<<<128, 512, SMEM_BYTES>>>(attn);

    proj_mma_kernel<<<dim3(64, 2), 256>>>(bc, out);
}

// round 17
// speedup vs baseline: 1.0423x; 1.0423x over previous
#include <cuda_runtime.h>
#include <cuda_fp16.h>

#define BB 2
#define SS 2048
#define DD 256
#define HH 8
#define DHD 32

// Scratch (allocation-free: device globals)
__device__ __half g_q[BB*HH*SS*DHD];
__device__ __half g_k[BB*HH*SS*DHD];
__device__ __half g_v[BB*HH*SS*DHD];
__device__ __half g_ctx[BB*SS*DD];
__device__ __half g_xh[BB*SS*DD];        // x converted to fp16
__device__ __half g_wh[3*DD*DD];         // wq|wk|wv fp16
__device__ __half g_wch[DD*DD];          // wc fp16
__device__ __half g_p[(size_t)BB*HH*SS*SS];  // per-head raw probs (fp16)
__device__ float  g_il[BB*HH*SS];        // per-head per-row 1/l

// ---------------------------------------------------------------------------
// helpers
// ---------------------------------------------------------------------------
__device__ __forceinline__ void mma_f16(float c[4], const unsigned a[4],
                                        unsigned b0, unsigned b1) {
    asm volatile(
        "mma.sync.aligned.m16n8k16.row.col.f32.f16.f16.f32 "
        "{%0,%1,%2,%3},{%4,%5,%6,%7},{%8,%9},{%0,%1,%2,%3};"
        : "+f"(c[0]), "+f"(c[1]), "+f"(c[2]), "+f"(c[3])
        : "r"(a[0]), "r"(a[1]), "r"(a[2]), "r"(a[3]), "r"(b0), "r"(b1));
}

__device__ __forceinline__ void ldsm_x2_t(unsigned& r0, unsigned& r1, const void* p) {
    unsigned addr = (unsigned)__cvta_generic_to_shared(p);
    asm volatile("ldmatrix.sync.aligned.m8n8.x2.trans.shared.b16 {%0,%1}, [%2];"
                 : "=r"(r0), "=r"(r1) : "r"(addr));
}

__device__ __forceinline__ float2 h2f(unsigned u) {
    return __half22float2(*(__half2*)&u);
}

__device__ __forceinline__ void cp16(void* dst, const void* src) {
    unsigned d = (unsigned)__cvta_generic_to_shared(dst);
    asm volatile("cp.async.cg.shared.global [%0], [%1], 16;" :: "r"(d), "l"(src));
}
#define CP_COMMIT() asm volatile("cp.async.commit_group;")
#define CP_WAIT1()  asm volatile("cp.async.wait_group 1;")
#define CP_WAIT0()  asm volatile("cp.async.wait_group 0;")

// ---------------------------------------------------------------------------
// fp32 -> fp16 conversion prologue (x, wq, wk, wv, wc)
// ---------------------------------------------------------------------------
__global__ __launch_bounds__(256) void convert_kernel(
    const float* __restrict__ x,
    const float* __restrict__ wq, const float* __restrict__ wk,
    const float* __restrict__ wv, const float* __restrict__ wc)
{
    int t = blockIdx.x * 256 + threadIdx.x;
    int e = t * 4;
    const float* src;
    __half* dst;
    if (e < BB*SS*DD) {
        src = x + e; dst = g_xh + e;
    } else {
        int r = e - BB*SS*DD;
        int wsel = r >> 16;
        int off = r & 65535;
        src = (wsel == 0 ? wq : wsel == 1 ? wk : wsel == 2 ? wv : wc) + off;
        dst = (wsel == 3 ? g_wch : g_wh + wsel * 65536) + off;
    }
    float4 v = *(const float4*)src;
    __half2* d2 = (__half2*)dst;
    d2[0] = __floats2half2_rn(v.x, v.y);
    d2[1] = __floats2half2_rn(v.z, v.w);
}

// ---------------------------------------------------------------------------
// fp16 GEMM staging for the projections: CTA tile M=64, N=128, k-chunk 32.
// ---------------------------------------------------------------------------
__device__ __forceinline__ void stage_gemm(const __half* A, const __half* B,
                                           __half* As, __half* Bs,
                                           int mt0, int nbase, int c, int tid)
{
    {   int row = tid >> 2, seg = tid & 3;
        cp16(As + row * 40 + seg * 8, A + (size_t)(mt0 + row) * 256 + c * 32 + seg * 8); }
    #pragma unroll
    for (int i = 0; i < 2; i++) {
        int id = i * 256 + tid;
        int row = id >> 2, seg = id & 3;
        cp16(Bs + row * 40 + seg * 8, B + (size_t)(nbase + row) * 256 + c * 32 + seg * 8);
    }
    CP_COMMIT();
}

// ---------------------------------------------------------------------------
// QKV projection via fp16 mma
// ---------------------------------------------------------------------------
__global__ __launch_bounds__(256, 2) void qkv_mma_kernel(
    const float* __restrict__ bq, const float* __restrict__ bk,
    const float* __restrict__ bv)
{
    __shared__ __half As[2][64*40];
    __shared__ __half Bs[2][128*40];
    const int tid = threadIdx.x, w = tid >> 5, lane = tid & 31;
    const int g = lane >> 2, tg = lane & 3;
    const int warpM = w >> 2, warpN = w & 3;
    const int mt0 = blockIdx.x * 64;
    const int y = blockIdx.y;
    const int wsel = y >> 1;
    const int nbase = (y & 1) * 128;
    const __half* Bw = g_wh + wsel * DD * DD;
    const float* bias = wsel == 0 ? bq : (wsel == 1 ? bk : bv);
    __half* dst = wsel == 0 ? g_q : (wsel == 1 ? g_k : g_v);

    float acc[2][4][4] = {};

    stage_gemm(g_xh, Bw, As[0], Bs[0], mt0, nbase, 0, tid);
    stage_gemm(g_xh, Bw, As[1], Bs[1], mt0, nbase, 1, tid);
    for (int c = 0; c < 8; c++) {
        if (c < 7) CP_WAIT1(); else CP_WAIT0();
        __syncthreads();
        const __half* Ab = As[c & 1];
        const __half* Bb = Bs[c & 1];
        #pragma unroll
        for (int ks = 0; ks < 2; ks++) {
            unsigned a[2][4], bf[4][2];
            #pragma unroll
            for (int mt = 0; mt < 2; mt++) {
                const __half* ar  = Ab + (warpM*32 + mt*16 + g) * 40 + ks*16 + 2*tg;
                const __half* ar8 = ar + 8 * 40;
                a[mt][0] = *(const unsigned*)ar;       a[mt][1] = *(const unsigned*)ar8;
                a[mt][2] = *(const unsigned*)(ar + 8); a[mt][3] = *(const unsigned*)(ar8 + 8);
            }
            #pragma unroll
            for (int nt = 0; nt < 4; nt++) {
                const __half* br = Bb + (warpN*32 + nt*8 + g) * 40 + ks*16 + 2*tg;
                bf[nt][0] = *(const unsigned*)br;
                bf[nt][1] = *(const unsigned*)(br + 8);
            }
            #pragma unroll
            for (int mt = 0; mt < 2; mt++)
                #pragma unroll
                for (int nt = 0; nt < 4; nt++)
                    mma_f16(acc[mt][nt], a[mt], bf[nt][0], bf[nt][1]);
        }
        __syncthreads();
        if (c + 2 < 8) stage_gemm(g_xh, Bw, As[c & 1], Bs[c & 1], mt0, nbase, c + 2, tid);
    }

    #pragma unroll
    for (int mt = 0; mt < 2; mt++)
        #pragma unroll
        for (int hf = 0; hf < 2; hf++) {
            int m = mt0 + warpM*32 + mt*16 + g + hf*8;
            int bidx = m >> 11, s = m & 2047;
            #pragma unroll
            for (int nt = 0; nt < 4; nt++) {
                int n = nbase + warpN*32 + nt*8 + 2*tg;
                float c0 = acc[mt][nt][hf*2+0] + bias[n];
                float c1 = acc[mt][nt][hf*2+1] + bias[n+1];
                int h = n >> 5, dh = n & 31;
                *(__half2*)&dst[(((size_t)(bidx*HH + h) * SS + s) * DHD) + dh] =
                    __floats2half2_rn(c0, c1);
            }
        }
}

// ---------------------------------------------------------------------------
// Output projection via fp16 mma
// ---------------------------------------------------------------------------
__global__ __launch_bounds__(256, 2) void proj_mma_kernel(
    const float* __restrict__ bc, float* __restrict__ out)
{
    __shared__ __half As[2][64*40];
    __shared__ __half Bs[2][128*40];
    const int tid = threadIdx.x, w = tid >> 5, lane = tid & 31;
    const int g = lane >> 2, tg = lane & 3;
    const int warpM = w >> 2, warpN = w & 3;
    const int mt0 = blockIdx.x * 64;
    const int nbase = blockIdx.y * 128;

    float acc[2][4][4] = {};

    stage_gemm(g_ctx, g_wch, As[0], Bs[0], mt0, nbase, 0, tid);
    stage_gemm(g_ctx, g_wch, As[1], Bs[1], mt0, nbase, 1, tid);
    for (int c = 0; c < 8; c++) {
        if (c < 7) CP_WAIT1(); else CP_WAIT0();
        __syncthreads();
        const __half* Ab = As[c & 1];
        const __half* Bb = Bs[c & 1];
        #pragma unroll
        for (int ks = 0; ks < 2; ks++) {
            unsigned a[2][4], bf[4][2];
            #pragma unroll
            for (int mt = 0; mt < 2; mt++) {
                const __half* ar  = Ab + (warpM*32 + mt*16 + g) * 40 + ks*16 + 2*tg;
                const __half* ar8 = ar + 8 * 40;
                a[mt][0] = *(const unsigned*)ar;       a[mt][1] = *(const unsigned*)ar8;
                a[mt][2] = *(const unsigned*)(ar + 8); a[mt][3] = *(const unsigned*)(ar8 + 8);
            }
            #pragma unroll
            for (int nt = 0; nt < 4; nt++) {
                const __half* br = Bb + (warpN*32 + nt*8 + g) * 40 + ks*16 + 2*tg;
                bf[nt][0] = *(const unsigned*)br;
                bf[nt][1] = *(const unsigned*)(br + 8);
            }
            #pragma unroll
            for (int mt = 0; mt < 2; mt++)
                #pragma unroll
                for (int nt = 0; nt < 4; nt++)
                    mma_f16(acc[mt][nt], a[mt], bf[nt][0], bf[nt][1]);
        }
        __syncthreads();
        if (c + 2 < 8) stage_gemm(g_ctx, g_wch, As[c & 1], Bs[c & 1], mt0, nbase, c + 2, tid);
    }

    #pragma unroll
    for (int mt = 0; mt < 2; mt++)
        #pragma unroll
        for (int hf = 0; hf < 2; hf++) {
            int m = mt0 + warpM*32 + mt*16 + g + hf*8;
            #pragma unroll
            for (int nt = 0; nt < 4; nt++) {
                int n = nbase + warpN*32 + nt*8 + 2*tg;
                float c0 = acc[mt][nt][hf*2+0] + bc[n];
                float c1 = acc[mt][nt][hf*2+1] + bc[n+1];
                *(float2*)&out[(size_t)m * 256 + n] = make_float2(c0, c1);
            }
        }
}

// ---------------------------------------------------------------------------
// Attention v8: R15 structure, but head-mean RMW replaced by a streaming fp16
// prob dump to g_p (+ invl to g_il). 503MB of fp32 L2 RMW -> 134MB fp16 writes.
// smem:
//   sS   [32][2056] fp16 = 131584  (scores/probs; aliased as sRd after PV)
//   buf0/buf1: 256 rows x 40 halfs = 20480B each
//   sQ   [32][40] fp16 = 2560        total 175104
// ---------------------------------------------------------------------------
#define SSH 2056
#define SMEM_BYTES (32*SSH*2 + 2*20480 + 32*40*2)

__device__ __forceinline__ void stage_kv(const __half* src, __half* dst, int tid) {
    #pragma unroll
    for (int i = 0; i < 2; i++) {
        int id = i * 512 + tid;
        int row = id >> 2, seg = id & 3;
        cp16(dst + row * 40 + seg * 8, src + row * 32 + seg * 8);
    }
    CP_COMMIT();
}

__global__ __launch_bounds__(512, 1) void attn_kernel()
{
    extern __shared__ char sm[];
    __half* sS = (__half*)sm;                         // 32 x 2056
    float*  sRd = (float*)sm;                         // aliases sS (dead at reduction)
    __half* buf0 = (__half*)(sm + 32 * SSH * 2);      // 256 x 40
    __half* buf1 = buf0 + 10240;
    __half* sQ   = buf1 + 10240;                      // 32 x 40
    __shared__ float s_invl[32];

    const int tid  = threadIdx.x;
    const int w    = tid >> 5;       // warp 0..15
    const int lane = tid & 31;
    const int g    = lane >> 2;
    const int tg   = lane & 3;
    const int b  = blockIdx.x >> 6;
    const int q0 = (blockIdx.x & 63) << 5;

    // prefetch K tiles 0,1 of head 0
    {
        const __half* kb0 = g_k + (size_t)(b * HH) * SS * DHD;
        stage_kv(kb0, buf0, tid);
        stage_kv(kb0 + 8192, buf1, tid);
    }

    for (int h = 0; h < HH; h++) {
        const __half* qb = g_q + ((size_t)(b * HH + h) * SS + q0) * DHD;
        const __half* kb = g_k + (size_t)(b * HH + h) * SS * DHD;
        const __half* vb = g_v + (size_t)(b * HH + h) * SS * DHD;
        const __half* kbn = g_k + (size_t)(b * HH + ((h + 1) & 7)) * SS * DHD;

        // --- Q tile (32x32), scale by 1/sqrt(32) ---
        const float scale = 0.17677669529663687f;
        {
            int r = tid >> 4, c2 = (tid & 15) * 2;
            float2 f = __half22float2(*(const __half2*)(qb + r * 32 + c2));
            *(__half2*)(sQ + r * 40 + c2) = __floats2half2_rn(f.x * scale, f.y * scale);
        }

        // --- scores: 8 tiles of 256 keys; warp owns 16-key n-slice per tile ---
        unsigned qa[2][2][4];     // [mtile][kc][frag]
        for (int kt = 0; kt < 8; kt++) {
            CP_WAIT1();
            __syncthreads();
            const __half* sK = (kt & 1) ? buf1 : buf0;
            if (kt == 0) {
                #pragma unroll
                for (int mt = 0; mt < 2; mt++)
                    #pragma unroll
                    for (int kc = 0; kc < 2; kc++) {
                        const __half* qr  = sQ + (mt*16 + g) * 40 + kc * 16 + 2 * tg;
                        const __half* qr8 = qr + 8 * 40;
                        qa[mt][kc][0] = *(const unsigned*)qr;
                        qa[mt][kc][1] = *(const unsigned*)qr8;
                        qa[mt][kc][2] = *(const unsigned*)(qr + 8);
                        qa[mt][kc][3] = *(const unsigned*)(qr8 + 8);
                    }
            }
            #pragma unroll
            for (int nt = 0; nt < 2; nt++) {
                const int n0 = w * 16 + nt * 8;
                const __half* krow = sK + (n0 + g) * 40;
                unsigned b0[2], b1[2];
                #pragma unroll
                for (int kc = 0; kc < 2; kc++) {
                    b0[kc] = *(const unsigned*)(krow + kc * 16 + 2 * tg);
                    b1[kc] = *(const unsigned*)(krow + kc * 16 + 2 * tg + 8);
                }
                #pragma unroll
                for (int mt = 0; mt < 2; mt++) {
                    float c[4] = {0.f, 0.f, 0.f, 0.f};
                    #pragma unroll
                    for (int kc = 0; kc < 2; kc++)
                        mma_f16(c, qa[mt][kc], b0[kc], b1[kc]);
                    const int col = kt * 256 + n0 + tg * 2;
                    *(__half2*)(sS + (mt*16 + g) * SSH + col)     = __floats2half2_rn(c[0], c[1]);
                    *(__half2*)(sS + (mt*16 + g + 8) * SSH + col) = __floats2half2_rn(c[2], c[3]);
                }
            }
            __syncthreads();
            if (kt < 6)       stage_kv(kb + (size_t)(kt + 2) * 8192, (kt & 1) ? buf1 : buf0, tid);
            else if (kt == 6) stage_kv(vb, buf0, tid);
            else              stage_kv(vb + 8192, buf1, tid);
        }
        __syncthreads();

        // --- softmax (fp32 math, fp16 storage); V tiles 0,1 loading behind it ---
        {
            const int row = tid >> 4, j = tid & 15;   // 32 rows x 16 threads
            uint4* r4 = (uint4*)(sS + (size_t)row * SSH);
            float mx = -1e30f;
            for (int k = j; k < 256; k += 16) {
                uint4 u = r4[k];
                float2 f0 = h2f(u.x), f1 = h2f(u.y), f2 = h2f(u.z), f3 = h2f(u.w);
                mx = fmaxf(mx, fmaxf(fmaxf(f0.x, f0.y), fmaxf(f1.x, f1.y)));
                mx = fmaxf(mx, fmaxf(fmaxf(f2.x, f2.y), fmaxf(f3.x, f3.y)));
            }
            #pragma unroll
            for (int o = 8; o; o >>= 1) mx = fmaxf(mx, __shfl_xor_sync(0xffffffffu, mx, o));
            float sum = 0.f;
            for (int k = j; k < 256; k += 16) {
                uint4 u = r4[k];
                float2 f0 = h2f(u.x), f1 = h2f(u.y), f2 = h2f(u.z), f3 = h2f(u.w);
                f0.x = __expf(f0.x - mx); f0.y = __expf(f0.y - mx);
                f1.x = __expf(f1.x - mx); f1.y = __expf(f1.y - mx);
                f2.x = __expf(f2.x - mx); f2.y = __expf(f2.y - mx);
                f3.x = __expf(f3.x - mx); f3.y = __expf(f3.y - mx);
                sum += (f0.x + f0.y) + (f1.x + f1.y) + (f2.x + f2.y) + (f3.x + f3.y);
                __half2 h0 = __floats2half2_rn(f0.x, f0.y);
                __half2 h1 = __floats2half2_rn(f1.x, f1.y);
                __half2 h2v = __floats2half2_rn(f2.x, f2.y);
                __half2 h3 = __floats2half2_rn(f3.x, f3.y);
                u.x = *(unsigned*)&h0; u.y = *(unsigned*)&h1;
                u.z = *(unsigned*)&h2v; u.w = *(unsigned*)&h3;
                r4[k] = u;
            }
            #pragma unroll
            for (int o = 8; o; o >>= 1) sum += __shfl_xor_sync(0xffffffffu, sum, o);
            if (j == 0) s_invl[row] = 1.0f / sum;
        }
        __syncthreads();

        // --- dump raw fp16 probs to g_p (streaming writes, no reads) + invl ---
        {
            uint4* p4 = (uint4*)(g_p + ((size_t)(b * HH + h) * SS + q0) * SS);
            for (int t = tid; t < 32 * 256; t += 512) {
                int r = t >> 8, c = t & 255;
                p4[r * 256 + c] = *(const uint4*)(sS + (size_t)r * SSH + c * 8);
            }
            if (tid < 32)
                g_il[(size_t)(b * HH + h) * SS + q0 + tid] = s_invl[tid];
        }

        // --- PV: 8 phases of 256 k; warp owns 16-key k-slice per phase ---
        float oc[2][4][4] = {};
        for (int p = 0; p < 8; p++) {
            CP_WAIT1();
            __syncthreads();
            const __half* sVh = (p & 1) ? buf1 : buf0;
            const int kr  = w * 16;
            const int ksg = p * 256 + kr;
            unsigned pa[2][4];
            #pragma unroll
            for (int mt = 0; mt < 2; mt++) {
                pa[mt][0] = *(const unsigned*)(sS + (mt*16 + g) * SSH + ksg + 2 * tg);
                pa[mt][1] = *(const unsigned*)(sS + (mt*16 + g + 8) * SSH + ksg + 2 * tg);
                pa[mt][2] = *(const unsigned*)(sS + (mt*16 + g) * SSH + ksg + 2 * tg + 8);
                pa[mt][3] = *(const unsigned*)(sS + (mt*16 + g + 8) * SSH + ksg + 2 * tg + 8);
            }
            const __half* vrow = sVh + (kr + (lane & 15)) * 40;
            #pragma unroll
            for (int nt = 0; nt < 4; nt++) {
                unsigned b0, b1;
                ldsm_x2_t(b0, b1, vrow + nt * 8);
                #pragma unroll
                for (int mt = 0; mt < 2; mt++)
                    mma_f16(oc[mt][nt], pa[mt], b0, b1);
            }
            __syncthreads();
            if (p < 6)       stage_kv(vb + (size_t)(p + 2) * 8192, (p & 1) ? buf1 : buf0, tid);
            else if (p == 6) stage_kv(kbn, buf0, tid);
            else             stage_kv(kbn + 8192, buf1, tid);
        }
        __syncthreads();   // PV consumers of sS done -> sRd may alias it

        // --- cross-warp reduction of the 16 k-partials (sRd aliases sS) ---
        #pragma unroll
        for (int mt = 0; mt < 2; mt++)
            #pragma unroll
            for (int nt = 0; nt < 4; nt++) {
                const int col = nt * 8 + tg * 2;
                sRd[w * 1024 + (mt*16 + g) * 32 + col]           = oc[mt][nt][0];
                sRd[w * 1024 + (mt*16 + g) * 32 + col + 1]       = oc[mt][nt][1];
                sRd[w * 1024 + (mt*16 + g + 8) * 32 + col]       = oc[mt][nt][2];
                sRd[w * 1024 + (mt*16 + g + 8) * 32 + col + 1]   = oc[mt][nt][3];
            }
        __syncthreads();
        for (int o = tid; o < 1024; o += 512) {
            int r = o >> 5, d = o & 31;
            float s = 0.f;
            #pragma unroll
            for (int e = 0; e < 16; e++) s += sRd[e * 1024 + o];
            g_ctx[(size_t)(b * SS + q0 + r) * DD + h * DHD + d] = __float2half(s * s_invl[r]);
        }
        __syncthreads();   // protect sRd/sQ/sS before next head
    }
    CP_WAIT0();   // drain trailing (dummy) prefetch before exit
}

// ---------------------------------------------------------------------------
// Head-mean: out[b,s,:] = sum_h p_h * (invl_h / 8).  Pure streaming.
// One block per (b, s) row; each thread covers 8 consecutive columns.
// ---------------------------------------------------------------------------
__global__ __launch_bounds__(256) void sum_kernel(float* __restrict__ out_attn)
{
    __shared__ float sc[HH];
    const int s = blockIdx.x & (SS - 1);
    const int b = blockIdx.x >> 11;
    const int c = threadIdx.x * 8;
    if (threadIdx.x < HH)
        sc[threadIdx.x] = g_il[(size_t)(b * HH + threadIdx.x) * SS + s] * 0.125f;
    __syncthreads();
    float acc[8] = {};
    #pragma unroll
    for (int h = 0; h < HH; h++) {
        const __half* pr = g_p + (((size_t)(b * HH + h) * SS + s) * SS) + c;
        uint4 u = *(const uint4*)pr;
        float f = sc[h];
        float2 a0 = h2f(u.x), a1 = h2f(u.y), a2 = h2f(u.z), a3 = h2f(u.w);
        acc[0] += a0.x * f; acc[1] += a0.y * f;
        acc[2] += a1.x * f; acc[3] += a1.y * f;
        acc[4] += a2.x * f; acc[5] += a2.y * f;
        acc[6] += a3.x * f; acc[7] += a3.y * f;
    }
    float4* o = (float4*)(out_attn + ((size_t)(b * SS + s)) * SS + c);
    o[0] = make_float4(acc[0], acc[1], acc[2], acc[3]);
    o[1] = make_float4(acc[4], acc[5], acc[6], acc[7]);
}

// ---------------------------------------------------------------------------
extern "C" void kernel_launch(void* const* d_in, const int* in_sizes, int n_in,
                              void* d_out, int out_size)
{
    const float* x  = (const float*)d_in[0];
    const float* wq = (const float*)d_in[1];
    const float* bq = (const float*)d_in[2];
    const float* wk = (const float*)d_in[3];
    const float* bk = (const float*)d_in[4];
    const float* wv = (const float*)d_in[5];
    const float* bv = (const float*)d_in[6];
    const float* wc = (const float*)d_in[7];
    const float* bc = (const float*)d_in[8];

    float* out  = (float*)d_out;
    float* attn = out + (size_t)BB * SS * DD;

    convert_kernel<<<1280, 256>>>(x, wq, wk, wv, wc);
    qkv_mma_kernel<<<dim3(64, 6), 256>>>(bq, bk, bv);

    cudaFuncSetAttribute(attn_kernel,
                         cudaFuncAttributeMaxDynamicSharedMemorySize,
                         SMEM_BYTES);
    attn_kernel<<<128, 512, SMEM_BYTES>>>();

    sum_kernel<<<BB * SS, 256>>>(attn);
    proj_mma_kernel<<<dim3(64, 2), 256>>>(bc, out);
}